// round 1
// baseline (speedup 1.0000x reference)
#include <cuda_runtime.h>
#include <cstdint>
#include <math.h>

// Problem constants
#define BB     64
#define D0     4096
#define D1     1024
#define D2OUT  1000
#define TT     32

// ---------------- device scratch (static globals; no runtime allocation) ----------------
__device__ float         g_Wt0[(size_t)D0 * D0];   // transposed w0: Wt0[i*D0 + j] = w0[j*D0 + i]
__device__ float         g_Wt2[(size_t)D1 * D1];   // transposed w2: Wt2[i*D1 + j] = w2[j*D1 + i], j<1000 valid
__device__ uint32_t      g_ord0[BB * D0];          // per-batch weight-column indices sorted by spike count n
__device__ int           g_seg0[BB * 34];          // bucket segment starts (34 = 33 buckets + end)
__device__ int           g_cnt0[BB * D0];          // layer-0 spike counts
__device__ unsigned char g_N1[BB * D1];            // layer-1 encoded counts
__device__ uint32_t      g_ord2[BB * D1];
__device__ int           g_seg2[BB * 34];
__device__ int           g_cnt2[BB * D2OUT];       // layer-2 spike counts

// ---------------- uniform spike pattern (matches reference fp32 semantics) ----------------
// spacing = fp32(32/n) (IEEE); spike at cycle c iff floor(c/spacing) < n  (always true for
// 1<=n<=31, c<=31: exact quotient <= 31n/32(1+eps) < n) and floor(fmod(c, spacing)) == 0.
// fmod of two fp32 values is exact; compute in double for exactness regardless of build flags.
__device__ __forceinline__ uint32_t pattern_mask(int n) {
    if (n <= 0)  return 0u;
    if (n >= TT) return 0xFFFFFFFFu;
    float spacing = __fdiv_rn(32.0f, (float)n);
    uint32_t m = 0u;
    for (int c = 0; c < TT; c++) {
        double r = fmod((double)c, (double)spacing);
        if (r < 1.0) m |= (1u << c);
    }
    return m;
}

// ---------------- transpose (tiled, padded smem) ----------------
template <int S>
__global__ void transpose_kernel(const float* __restrict__ src) {
    constexpr int rows = (S == 1) ? D0 : D2OUT;   // src rows
    constexpr int cols = (S == 1) ? D0 : D1;      // src cols
    constexpr int ldd  = (S == 1) ? D0 : D1;      // dst row stride
    float* dst = (S == 1) ? g_Wt0 : g_Wt2;

    __shared__ float tile[32][33];
    int c0 = blockIdx.x * 32, r0 = blockIdx.y * 32;
    int cx = c0 + threadIdx.x;
#pragma unroll
    for (int dy = 0; dy < 32; dy += 8) {
        int r = r0 + threadIdx.y + dy;
        if (r < rows && cx < cols)
            tile[threadIdx.y + dy][threadIdx.x] = src[(size_t)r * cols + cx];
    }
    __syncthreads();
    int rx = r0 + threadIdx.x;
#pragma unroll
    for (int dy = 0; dy < 32; dy += 8) {
        int c = c0 + threadIdx.y + dy;
        if (c < cols && rx < rows)
            dst[(size_t)c * ldd + rx] = tile[threadIdx.x][threadIdx.y + dy];
    }
}

// ---------------- deterministic warp counting sort (32 threads, stable-by-lane-block) ----------------
__device__ void counting_sort_warp(const unsigned char* ns, int K,
                                   uint32_t* ord_out, int* seg_out) {
    int lane = threadIdx.x;
    int per = K >> 5;
    int lc[33];
    for (int n = 0; n < 33; n++) lc[n] = 0;
    for (int c = 0; c < per; c++) lc[ns[lane * per + c]]++;
    int off[33];
    int base = 0;
    for (int n = 0; n < 33; n++) {
        int v = lc[n];
        int s = v;
#pragma unroll
        for (int d = 1; d < 32; d <<= 1) {
            int o = __shfl_up_sync(0xffffffffu, s, d);
            if (lane >= d) s += o;
        }
        int tot = __shfl_sync(0xffffffffu, s, 31);
        off[n] = base + s - v;        // exclusive across lanes + bucket base
        if (lane == 0) seg_out[n] = base;
        base += tot;
    }
    if (lane == 0) seg_out[33] = base;  // == K
    for (int c = 0; c < per; c++) {
        int i = lane * per + c;
        int n = ns[i];
        ord_out[off[n]++] = (uint32_t)i;
    }
}

// layer-0 encode + sort: n(b, i') = round_half_even(32 * x[b, idx0[i']])
__global__ void sort1_kernel(const float* __restrict__ x, const int* __restrict__ idx0) {
    __shared__ unsigned char ns[D0];
    int b = blockIdx.x, lane = threadIdx.x;
    for (int i = lane; i < D0; i += 32) {
        float r = x[b * D0 + idx0[i]];
        ns[i] = (unsigned char)__float2int_rn(r * 32.0f);
    }
    __syncwarp();
    counting_sort_warp(ns, D0, g_ord0 + b * D0, g_seg0 + b * 34);
}

// layer-2 sort: n(b, i') = N1[b, idx2[i']]
__global__ void sort2_kernel(const int* __restrict__ idx2) {
    __shared__ unsigned char ns[D1];
    int b = blockIdx.x, lane = threadIdx.x;
    for (int i = lane; i < D1; i += 32) {
        ns[i] = g_N1[b * D1 + idx2[i]];
    }
    __syncwarp();
    counting_sort_warp(ns, D1, g_ord2 + b * D1, g_seg2 + b * 34);
}

// ---------------- main LIF kernel (segmented bucket reduction + pattern combine + scan) ----------------
template <int S>
__global__ void lif_main_kernel(const float* __restrict__ thr_p) {
    constexpr int K    = (S == 1) ? D0 : D1;
    constexpr int ldw  = (S == 1) ? D0 : D1;
    constexpr int Jmax = (S == 1) ? D0 : D2OUT;
    const float*    Wt      = (S == 1) ? g_Wt0 : g_Wt2;
    const uint32_t* ord     = (S == 1) ? g_ord0 : g_ord2;
    const int*      seg     = (S == 1) ? g_seg0 : g_seg2;
    int*            cnt_out = (S == 1) ? g_cnt0 : g_cnt2;

    __shared__ uint32_t spat[33];
    __shared__ int sseg[34];
    int tid = threadIdx.x;
    if (tid < 33) spat[tid] = pattern_mask(tid);
    if (tid < 34) sseg[tid] = seg[blockIdx.y * 34 + tid];
    __syncthreads();

    int b = blockIdx.y;
    int j = blockIdx.x * blockDim.x + tid;
    bool valid = (j < Jmax);
    int jc = valid ? j : 0;                 // clamp so loads stay in-bounds; store is guarded
    const float* Wj = Wt + jc;
    const uint32_t* po = ord + b * K;

    float I[TT];
#pragma unroll
    for (int t = 0; t < TT; t++) I[t] = 0.f;

    // buckets n = 1..32 (n = 0 has an all-zero pattern -> contributes nothing, skip its loads)
    for (int n = 1; n < 33; n++) {
        int s = sseg[n], e = sseg[n + 1];
        if (s >= e) continue;
        float a0 = 0.f, a1 = 0.f, a2 = 0.f, a3 = 0.f;
        int k = s;
        for (; k + 4 <= e; k += 4) {
            int i0 = (int)po[k], i1 = (int)po[k + 1], i2 = (int)po[k + 2], i3 = (int)po[k + 3];
            float w0v = Wj[i0 * ldw];
            float w1v = Wj[i1 * ldw];
            float w2v = Wj[i2 * ldw];
            float w3v = Wj[i3 * ldw];
            a0 += w0v; a1 += w1v; a2 += w2v; a3 += w3v;
        }
        for (; k < e; k++) a0 += Wj[(int)po[k] * ldw];
        float acc = (a0 + a1) + (a2 + a3);
        uint32_t m = spat[n];
#pragma unroll
        for (int t = 0; t < TT; t++)
            if ((m >> t) & 1u) I[t] += acc;
    }

    // LIF scan: memb += I[t]; fired = thr < memb; memb -= thr on fire
    float thr = *thr_p;
    float memb = 0.f;
    int cnt = 0;
#pragma unroll
    for (int t = 0; t < TT; t++) {
        memb += I[t];
        if (memb > thr) { memb -= thr; cnt++; }
    }
    if (valid) cnt_out[b * Jmax + j] = cnt;
}

// ---------------- pooling + layer-1 re-encoding (all-exact integer/pow2 arithmetic) ----------------
__global__ void mid_kernel(const int* __restrict__ idx1) {
    int b = blockIdx.x, p = threadIdx.x;   // p in [0,1024)
    int ch = p >> 4, oh = (p >> 2) & 3, ow = p & 3;
    int c = 0;
#pragma unroll
    for (int dh = 0; dh < 2; dh++)
#pragma unroll
        for (int dw = 0; dw < 2; dw++) {
            int k = ch * 64 + (2 * oh + dh) * 8 + (2 * ow + dw);
            c += g_cnt0[b * D0 + idx1[k]];
        }
    // y_rate*32 == c/4 exactly in the reference; round half-to-even matches jnp.round
    g_N1[b * D1 + p] = (unsigned char)__float2int_rn((float)c * 0.25f);
}

// ---------------- output gather (spike counts as float) ----------------
__global__ void out_kernel(const int* __restrict__ idx_out, float* __restrict__ out) {
    int b = blockIdx.x, j = threadIdx.x;
    if (j < D2OUT) out[b * D2OUT + j] = (float)g_cnt2[b * D2OUT + idx_out[j]];
}

// ---------------- launch ----------------
extern "C" void kernel_launch(void* const* d_in, const int* in_sizes, int n_in,
                              void* d_out, int out_size) {
    (void)in_sizes; (void)n_in; (void)out_size;
    const float* x       = (const float*)d_in[0];
    const float* w0      = (const float*)d_in[1];
    const float* t0      = (const float*)d_in[2];
    const float* w2      = (const float*)d_in[3];
    const float* t2      = (const float*)d_in[4];
    const int*   idx0    = (const int*)d_in[5];
    const int*   idx1    = (const int*)d_in[6];
    const int*   idx2    = (const int*)d_in[7];
    const int*   idx_out = (const int*)d_in[8];
    float* out = (float*)d_out;

    dim3 tb(32, 8);
    transpose_kernel<1><<<dim3(D0 / 32, D0 / 32), tb>>>(w0);
    transpose_kernel<2><<<dim3(D1 / 32, (D2OUT + 31) / 32), tb>>>(w2);

    sort1_kernel<<<BB, 32>>>(x, idx0);
    lif_main_kernel<1><<<dim3(D0 / 256, BB), 256>>>(t0);

    mid_kernel<<<BB, D1>>>(idx1);
    sort2_kernel<<<BB, 32>>>(idx2);
    lif_main_kernel<2><<<dim3(4, BB), 256>>>(t2);

    out_kernel<<<BB, 1024>>>(idx_out, out);
}